// round 9
// baseline (speedup 1.0000x reference)
#include <cuda_runtime.h>
#include <math.h>

// LinearTimeMMDLoss — single persistent fused kernel.
// Per pair (one warp): 16 front-batched float4 loads, FMA distance sums,
// butterfly reduce (all lanes get dxx,dyy,dxy,dyx), then the 20-term exp
// epilogue is PARALLELIZED across lanes (lane j: kernel k=j/4, term t=j%4),
// one expf per lane, butterfly-sum, lane 0 accumulates in double.
// Persistent 296-block grid -> no wave transitions; loads stream continuously.

#define D 512
#define D4 (D / 4)                 // 128 float4 per row
#define THREADS 256
#define WARPS_PER_BLOCK 8
#define GRID_BLOCKS 296            // 2 per SM, persistent

__device__ double g_partials[GRID_BLOCKS];
__device__ int    g_done = 0;      // reset by last block each call (graph-safe)

__global__ void __launch_bounds__(THREADS, 2) mmd_fused_kernel(
    const float* __restrict__ source,
    const float* __restrict__ target,
    float* __restrict__ out,
    int m2, int num_blocks)
{
    const int warp_id = threadIdx.x >> 5;
    const int lane    = threadIdx.x & 31;
    const int gw      = blockIdx.x * WARPS_PER_BLOCK + warp_id;
    const int nw      = num_blocks * WARPS_PER_BLOCK;

    // per-lane epilogue constants (lane j handles kernel k=j/4, term t=j%4)
    const int  ek    = lane >> 2;            // 0..7 (only <5 used)
    const int  et    = lane & 3;             // 0..3
    const bool eact  = (ek < 5);
    const float emul = (float)(1 << (ek < 5 ? ek : 0));      // 2^k
    const float esgn = (et < 2) ? 1.0f : -1.0f;              // + + - -

    double h_acc = 0.0;

    for (int pair = gw; pair < m2; pair += nw) {
        const float4* __restrict__ xo =
            (const float4*)(source + (size_t)(2 * pair) * D) + lane;
        const float4* __restrict__ xe = xo + D4;
        const float4* __restrict__ yo =
            (const float4*)(target + (size_t)(2 * pair) * D) + lane;
        const float4* __restrict__ ye = yo + D4;

        // front-batch all 16 independent float4 loads
        float4 A0 = xo[0], A1 = xo[32], A2 = xo[64], A3 = xo[96];
        float4 B0 = xe[0], B1 = xe[32], B2 = xe[64], B3 = xe[96];
        float4 C0 = yo[0], C1 = yo[32], C2 = yo[64], C3 = yo[96];
        float4 E0 = ye[0], E1 = ye[32], E2 = ye[64], E3 = ye[96];

        float dxx = 0.f, dyy = 0.f, dxy = 0.f, dyx = 0.f;
        float t;

        #define ACC4(a, b, acc) \
            t = a.x - b.x; acc = fmaf(t, t, acc); \
            t = a.y - b.y; acc = fmaf(t, t, acc); \
            t = a.z - b.z; acc = fmaf(t, t, acc); \
            t = a.w - b.w; acc = fmaf(t, t, acc);

        ACC4(A0, B0, dxx)  ACC4(A1, B1, dxx)  ACC4(A2, B2, dxx)  ACC4(A3, B3, dxx)
        ACC4(C0, E0, dyy)  ACC4(C1, E1, dyy)  ACC4(C2, E2, dyy)  ACC4(C3, E3, dyy)
        ACC4(A0, E0, dxy)  ACC4(A1, E1, dxy)  ACC4(A2, E2, dxy)  ACC4(A3, E3, dxy)
        ACC4(B0, C0, dyx)  ACC4(B1, C1, dyx)  ACC4(B2, C2, dyx)  ACC4(B3, C3, dyx)
        #undef ACC4

        // butterfly reduce: ALL lanes end with the four full sums
        #pragma unroll
        for (int off = 16; off > 0; off >>= 1) {
            dxx += __shfl_xor_sync(0xffffffffu, dxx, off);
            dyy += __shfl_xor_sync(0xffffffffu, dyy, off);
            dxy += __shfl_xor_sync(0xffffffffu, dxy, off);
            dyx += __shfl_xor_sync(0xffffffffu, dyx, off);
        }

        // lane-parallel exp epilogue: one term per lane (20 active lanes)
        float hterm = 0.0f;
        if (eact) {
            float bw = (dxx + dyy + dxy + dyx) * (0.25f * 0.25f);
            float b  = fmaf(bw, emul, 1e-6f);
            float d  = (et == 0) ? dxx : (et == 1) ? dyy : (et == 2) ? dxy : dyx;
            hterm = esgn * expf(-d / b);
        }
        #pragma unroll
        for (int off = 16; off > 0; off >>= 1)
            hterm += __shfl_xor_sync(0xffffffffu, hterm, off);

        if (lane == 0) h_acc += (double)hterm;
    }

    // ---- block partial + single-pass finish ----
    __shared__ double s_h[WARPS_PER_BLOCK];
    __shared__ bool   s_last;
    if (lane == 0) s_h[warp_id] = h_acc;
    __syncthreads();

    if (threadIdx.x == 0) {
        double sum = 0.0;
        #pragma unroll
        for (int w = 0; w < WARPS_PER_BLOCK; w++) sum += s_h[w];
        g_partials[blockIdx.x] = sum;
        __threadfence();
        int prev = atomicAdd(&g_done, 1);
        s_last = (prev == num_blocks - 1);
    }
    __syncthreads();

    if (s_last) {
        __shared__ double s_r[THREADS];
        double v = 0.0;
        for (int i = threadIdx.x; i < num_blocks; i += THREADS)
            v += g_partials[i];
        s_r[threadIdx.x] = v;
        __syncthreads();
        #pragma unroll
        for (int off = THREADS / 2; off > 0; off >>= 1) {
            if (threadIdx.x < off) s_r[threadIdx.x] += s_r[threadIdx.x + off];
            __syncthreads();
        }
        if (threadIdx.x == 0) {
            out[0] = (float)(s_r[0] / (double)m2);
            g_done = 0;               // reset for next graph replay
            __threadfence();
        }
    }
}

extern "C" void kernel_launch(void* const* d_in, const int* in_sizes, int n_in,
                              void* d_out, int out_size)
{
    const float* source = (const float*)d_in[0];
    const float* target = (const float*)d_in[1];
    float* out = (float*)d_out;

    const int m  = in_sizes[0] / D;   // 65536
    const int m2 = m / 2;             // 32768

    mmd_fused_kernel<<<GRID_BLOCKS, THREADS>>>(source, target, out, m2, GRID_BLOCKS);
}

// round 10
// speedup vs baseline: 1.0047x; 1.0047x over previous
#include <cuda_runtime.h>
#include <math.h>

// LinearTimeMMDLoss — single persistent fused kernel.
// Per pair (one warp): 16 front-batched float4 loads, FMA distance sums,
// butterfly reduce (all lanes get dxx,dyy,dxy,dyx), then the 20-term exp
// epilogue is PARALLELIZED across lanes (lane j: kernel k=j/4, term t=j%4),
// one expf per lane, butterfly-sum, lane 0 accumulates in double.
// Persistent 296-block grid -> no wave transitions; loads stream continuously.

#define D 512
#define D4 (D / 4)                 // 128 float4 per row
#define THREADS 256
#define WARPS_PER_BLOCK 8
#define GRID_BLOCKS 296            // 2 per SM, persistent

__device__ double g_partials[GRID_BLOCKS];
__device__ int    g_done = 0;      // reset by last block each call (graph-safe)

__global__ void __launch_bounds__(THREADS, 2) mmd_fused_kernel(
    const float* __restrict__ source,
    const float* __restrict__ target,
    float* __restrict__ out,
    int m2, int num_blocks)
{
    const int warp_id = threadIdx.x >> 5;
    const int lane    = threadIdx.x & 31;
    const int gw      = blockIdx.x * WARPS_PER_BLOCK + warp_id;
    const int nw      = num_blocks * WARPS_PER_BLOCK;

    // per-lane epilogue constants (lane j handles kernel k=j/4, term t=j%4)
    const int  ek    = lane >> 2;            // 0..7 (only <5 used)
    const int  et    = lane & 3;             // 0..3
    const bool eact  = (ek < 5);
    const float emul = (float)(1 << (ek < 5 ? ek : 0));      // 2^k
    const float esgn = (et < 2) ? 1.0f : -1.0f;              // + + - -

    double h_acc = 0.0;

    for (int pair = gw; pair < m2; pair += nw) {
        const float4* __restrict__ xo =
            (const float4*)(source + (size_t)(2 * pair) * D) + lane;
        const float4* __restrict__ xe = xo + D4;
        const float4* __restrict__ yo =
            (const float4*)(target + (size_t)(2 * pair) * D) + lane;
        const float4* __restrict__ ye = yo + D4;

        // front-batch all 16 independent float4 loads
        float4 A0 = xo[0], A1 = xo[32], A2 = xo[64], A3 = xo[96];
        float4 B0 = xe[0], B1 = xe[32], B2 = xe[64], B3 = xe[96];
        float4 C0 = yo[0], C1 = yo[32], C2 = yo[64], C3 = yo[96];
        float4 E0 = ye[0], E1 = ye[32], E2 = ye[64], E3 = ye[96];

        float dxx = 0.f, dyy = 0.f, dxy = 0.f, dyx = 0.f;
        float t;

        #define ACC4(a, b, acc) \
            t = a.x - b.x; acc = fmaf(t, t, acc); \
            t = a.y - b.y; acc = fmaf(t, t, acc); \
            t = a.z - b.z; acc = fmaf(t, t, acc); \
            t = a.w - b.w; acc = fmaf(t, t, acc);

        ACC4(A0, B0, dxx)  ACC4(A1, B1, dxx)  ACC4(A2, B2, dxx)  ACC4(A3, B3, dxx)
        ACC4(C0, E0, dyy)  ACC4(C1, E1, dyy)  ACC4(C2, E2, dyy)  ACC4(C3, E3, dyy)
        ACC4(A0, E0, dxy)  ACC4(A1, E1, dxy)  ACC4(A2, E2, dxy)  ACC4(A3, E3, dxy)
        ACC4(B0, C0, dyx)  ACC4(B1, C1, dyx)  ACC4(B2, C2, dyx)  ACC4(B3, C3, dyx)
        #undef ACC4

        // butterfly reduce: ALL lanes end with the four full sums
        #pragma unroll
        for (int off = 16; off > 0; off >>= 1) {
            dxx += __shfl_xor_sync(0xffffffffu, dxx, off);
            dyy += __shfl_xor_sync(0xffffffffu, dyy, off);
            dxy += __shfl_xor_sync(0xffffffffu, dxy, off);
            dyx += __shfl_xor_sync(0xffffffffu, dyx, off);
        }

        // lane-parallel exp epilogue: one term per lane (20 active lanes)
        float hterm = 0.0f;
        if (eact) {
            float bw = (dxx + dyy + dxy + dyx) * (0.25f * 0.25f);
            float b  = fmaf(bw, emul, 1e-6f);
            float d  = (et == 0) ? dxx : (et == 1) ? dyy : (et == 2) ? dxy : dyx;
            hterm = esgn * expf(-d / b);
        }
        #pragma unroll
        for (int off = 16; off > 0; off >>= 1)
            hterm += __shfl_xor_sync(0xffffffffu, hterm, off);

        if (lane == 0) h_acc += (double)hterm;
    }

    // ---- block partial + single-pass finish ----
    __shared__ double s_h[WARPS_PER_BLOCK];
    __shared__ bool   s_last;
    if (lane == 0) s_h[warp_id] = h_acc;
    __syncthreads();

    if (threadIdx.x == 0) {
        double sum = 0.0;
        #pragma unroll
        for (int w = 0; w < WARPS_PER_BLOCK; w++) sum += s_h[w];
        g_partials[blockIdx.x] = sum;
        __threadfence();
        int prev = atomicAdd(&g_done, 1);
        s_last = (prev == num_blocks - 1);
    }
    __syncthreads();

    if (s_last) {
        __shared__ double s_r[THREADS];
        double v = 0.0;
        for (int i = threadIdx.x; i < num_blocks; i += THREADS)
            v += g_partials[i];
        s_r[threadIdx.x] = v;
        __syncthreads();
        #pragma unroll
        for (int off = THREADS / 2; off > 0; off >>= 1) {
            if (threadIdx.x < off) s_r[threadIdx.x] += s_r[threadIdx.x + off];
            __syncthreads();
        }
        if (threadIdx.x == 0) {
            out[0] = (float)(s_r[0] / (double)m2);
            g_done = 0;               // reset for next graph replay
            __threadfence();
        }
    }
}

extern "C" void kernel_launch(void* const* d_in, const int* in_sizes, int n_in,
                              void* d_out, int out_size)
{
    const float* source = (const float*)d_in[0];
    const float* target = (const float*)d_in[1];
    float* out = (float*)d_out;

    const int m  = in_sizes[0] / D;   // 65536
    const int m2 = m / 2;             // 32768

    mmd_fused_kernel<<<GRID_BLOCKS, THREADS>>>(source, target, out, m2, GRID_BLOCKS);
}

// round 11
// speedup vs baseline: 1.0149x; 1.0102x over previous
#include <cuda_runtime.h>
#include <math.h>

// LinearTimeMMDLoss — single persistent fused kernel.
// Per pair (one warp): 16 front-batched float4 loads, FMA distance sums,
// butterfly reduce (all lanes get dxx,dyy,dxy,dyx), then the 20-term exp
// epilogue is PARALLELIZED across lanes (lane j: kernel k=j/4, term t=j%4),
// one expf per lane, butterfly-sum, lane 0 accumulates in double.
// Persistent 296-block grid -> no wave transitions; loads stream continuously.

#define D 512
#define D4 (D / 4)                 // 128 float4 per row
#define THREADS 256
#define WARPS_PER_BLOCK 8
#define GRID_BLOCKS 296            // 2 per SM, persistent

__device__ double g_partials[GRID_BLOCKS];
__device__ int    g_done = 0;      // reset by last block each call (graph-safe)

__global__ void __launch_bounds__(THREADS, 2) mmd_fused_kernel(
    const float* __restrict__ source,
    const float* __restrict__ target,
    float* __restrict__ out,
    int m2, int num_blocks)
{
    const int warp_id = threadIdx.x >> 5;
    const int lane    = threadIdx.x & 31;
    const int gw      = blockIdx.x * WARPS_PER_BLOCK + warp_id;
    const int nw      = num_blocks * WARPS_PER_BLOCK;

    // per-lane epilogue constants (lane j handles kernel k=j/4, term t=j%4)
    const int  ek    = lane >> 2;            // 0..7 (only <5 used)
    const int  et    = lane & 3;             // 0..3
    const bool eact  = (ek < 5);
    const float emul = (float)(1 << (ek < 5 ? ek : 0));      // 2^k
    const float esgn = (et < 2) ? 1.0f : -1.0f;              // + + - -

    double h_acc = 0.0;

    for (int pair = gw; pair < m2; pair += nw) {
        const float4* __restrict__ xo =
            (const float4*)(source + (size_t)(2 * pair) * D) + lane;
        const float4* __restrict__ xe = xo + D4;
        const float4* __restrict__ yo =
            (const float4*)(target + (size_t)(2 * pair) * D) + lane;
        const float4* __restrict__ ye = yo + D4;

        // front-batch all 16 independent float4 loads
        float4 A0 = xo[0], A1 = xo[32], A2 = xo[64], A3 = xo[96];
        float4 B0 = xe[0], B1 = xe[32], B2 = xe[64], B3 = xe[96];
        float4 C0 = yo[0], C1 = yo[32], C2 = yo[64], C3 = yo[96];
        float4 E0 = ye[0], E1 = ye[32], E2 = ye[64], E3 = ye[96];

        float dxx = 0.f, dyy = 0.f, dxy = 0.f, dyx = 0.f;
        float t;

        #define ACC4(a, b, acc) \
            t = a.x - b.x; acc = fmaf(t, t, acc); \
            t = a.y - b.y; acc = fmaf(t, t, acc); \
            t = a.z - b.z; acc = fmaf(t, t, acc); \
            t = a.w - b.w; acc = fmaf(t, t, acc);

        ACC4(A0, B0, dxx)  ACC4(A1, B1, dxx)  ACC4(A2, B2, dxx)  ACC4(A3, B3, dxx)
        ACC4(C0, E0, dyy)  ACC4(C1, E1, dyy)  ACC4(C2, E2, dyy)  ACC4(C3, E3, dyy)
        ACC4(A0, E0, dxy)  ACC4(A1, E1, dxy)  ACC4(A2, E2, dxy)  ACC4(A3, E3, dxy)
        ACC4(B0, C0, dyx)  ACC4(B1, C1, dyx)  ACC4(B2, C2, dyx)  ACC4(B3, C3, dyx)
        #undef ACC4

        // butterfly reduce: ALL lanes end with the four full sums
        #pragma unroll
        for (int off = 16; off > 0; off >>= 1) {
            dxx += __shfl_xor_sync(0xffffffffu, dxx, off);
            dyy += __shfl_xor_sync(0xffffffffu, dyy, off);
            dxy += __shfl_xor_sync(0xffffffffu, dxy, off);
            dyx += __shfl_xor_sync(0xffffffffu, dyx, off);
        }

        // lane-parallel exp epilogue: one term per lane (20 active lanes)
        float hterm = 0.0f;
        if (eact) {
            float bw = (dxx + dyy + dxy + dyx) * (0.25f * 0.25f);
            float b  = fmaf(bw, emul, 1e-6f);
            float d  = (et == 0) ? dxx : (et == 1) ? dyy : (et == 2) ? dxy : dyx;
            hterm = esgn * expf(-d / b);
        }
        #pragma unroll
        for (int off = 16; off > 0; off >>= 1)
            hterm += __shfl_xor_sync(0xffffffffu, hterm, off);

        if (lane == 0) h_acc += (double)hterm;
    }

    // ---- block partial + single-pass finish ----
    __shared__ double s_h[WARPS_PER_BLOCK];
    __shared__ bool   s_last;
    if (lane == 0) s_h[warp_id] = h_acc;
    __syncthreads();

    if (threadIdx.x == 0) {
        double sum = 0.0;
        #pragma unroll
        for (int w = 0; w < WARPS_PER_BLOCK; w++) sum += s_h[w];
        g_partials[blockIdx.x] = sum;
        __threadfence();
        int prev = atomicAdd(&g_done, 1);
        s_last = (prev == num_blocks - 1);
    }
    __syncthreads();

    if (s_last) {
        __shared__ double s_r[THREADS];
        double v = 0.0;
        for (int i = threadIdx.x; i < num_blocks; i += THREADS)
            v += g_partials[i];
        s_r[threadIdx.x] = v;
        __syncthreads();
        #pragma unroll
        for (int off = THREADS / 2; off > 0; off >>= 1) {
            if (threadIdx.x < off) s_r[threadIdx.x] += s_r[threadIdx.x + off];
            __syncthreads();
        }
        if (threadIdx.x == 0) {
            out[0] = (float)(s_r[0] / (double)m2);
            g_done = 0;               // reset for next graph replay
            __threadfence();
        }
    }
}

extern "C" void kernel_launch(void* const* d_in, const int* in_sizes, int n_in,
                              void* d_out, int out_size)
{
    const float* source = (const float*)d_in[0];
    const float* target = (const float*)d_in[1];
    float* out = (float*)d_out;

    const int m  = in_sizes[0] / D;   // 65536
    const int m2 = m / 2;             // 32768

    mmd_fused_kernel<<<GRID_BLOCKS, THREADS>>>(source, target, out, m2, GRID_BLOCKS);
}

// round 12
// speedup vs baseline: 1.0254x; 1.0103x over previous
#include <cuda_runtime.h>
#include <math.h>

// LinearTimeMMDLoss — single persistent fused kernel.
// Per pair (one warp): 16 front-batched float4 loads, FMA distance sums,
// butterfly reduce (all lanes get dxx,dyy,dxy,dyx), then the 20-term exp
// epilogue is PARALLELIZED across lanes (lane j: kernel k=j/4, term t=j%4),
// one expf per lane, butterfly-sum, lane 0 accumulates in double.
// Persistent 296-block grid -> no wave transitions; loads stream continuously.

#define D 512
#define D4 (D / 4)                 // 128 float4 per row
#define THREADS 256
#define WARPS_PER_BLOCK 8
#define GRID_BLOCKS 296            // 2 per SM, persistent

__device__ double g_partials[GRID_BLOCKS];
__device__ int    g_done = 0;      // reset by last block each call (graph-safe)

__global__ void __launch_bounds__(THREADS, 2) mmd_fused_kernel(
    const float* __restrict__ source,
    const float* __restrict__ target,
    float* __restrict__ out,
    int m2, int num_blocks)
{
    const int warp_id = threadIdx.x >> 5;
    const int lane    = threadIdx.x & 31;
    const int gw      = blockIdx.x * WARPS_PER_BLOCK + warp_id;
    const int nw      = num_blocks * WARPS_PER_BLOCK;

    // per-lane epilogue constants (lane j handles kernel k=j/4, term t=j%4)
    const int  ek    = lane >> 2;            // 0..7 (only <5 used)
    const int  et    = lane & 3;             // 0..3
    const bool eact  = (ek < 5);
    const float emul = (float)(1 << (ek < 5 ? ek : 0));      // 2^k
    const float esgn = (et < 2) ? 1.0f : -1.0f;              // + + - -

    double h_acc = 0.0;

    for (int pair = gw; pair < m2; pair += nw) {
        const float4* __restrict__ xo =
            (const float4*)(source + (size_t)(2 * pair) * D) + lane;
        const float4* __restrict__ xe = xo + D4;
        const float4* __restrict__ yo =
            (const float4*)(target + (size_t)(2 * pair) * D) + lane;
        const float4* __restrict__ ye = yo + D4;

        // front-batch all 16 independent float4 loads
        float4 A0 = xo[0], A1 = xo[32], A2 = xo[64], A3 = xo[96];
        float4 B0 = xe[0], B1 = xe[32], B2 = xe[64], B3 = xe[96];
        float4 C0 = yo[0], C1 = yo[32], C2 = yo[64], C3 = yo[96];
        float4 E0 = ye[0], E1 = ye[32], E2 = ye[64], E3 = ye[96];

        float dxx = 0.f, dyy = 0.f, dxy = 0.f, dyx = 0.f;
        float t;

        #define ACC4(a, b, acc) \
            t = a.x - b.x; acc = fmaf(t, t, acc); \
            t = a.y - b.y; acc = fmaf(t, t, acc); \
            t = a.z - b.z; acc = fmaf(t, t, acc); \
            t = a.w - b.w; acc = fmaf(t, t, acc);

        ACC4(A0, B0, dxx)  ACC4(A1, B1, dxx)  ACC4(A2, B2, dxx)  ACC4(A3, B3, dxx)
        ACC4(C0, E0, dyy)  ACC4(C1, E1, dyy)  ACC4(C2, E2, dyy)  ACC4(C3, E3, dyy)
        ACC4(A0, E0, dxy)  ACC4(A1, E1, dxy)  ACC4(A2, E2, dxy)  ACC4(A3, E3, dxy)
        ACC4(B0, C0, dyx)  ACC4(B1, C1, dyx)  ACC4(B2, C2, dyx)  ACC4(B3, C3, dyx)
        #undef ACC4

        // butterfly reduce: ALL lanes end with the four full sums
        #pragma unroll
        for (int off = 16; off > 0; off >>= 1) {
            dxx += __shfl_xor_sync(0xffffffffu, dxx, off);
            dyy += __shfl_xor_sync(0xffffffffu, dyy, off);
            dxy += __shfl_xor_sync(0xffffffffu, dxy, off);
            dyx += __shfl_xor_sync(0xffffffffu, dyx, off);
        }

        // lane-parallel exp epilogue: one term per lane (20 active lanes)
        float hterm = 0.0f;
        if (eact) {
            float bw = (dxx + dyy + dxy + dyx) * (0.25f * 0.25f);
            float b  = fmaf(bw, emul, 1e-6f);
            float d  = (et == 0) ? dxx : (et == 1) ? dyy : (et == 2) ? dxy : dyx;
            hterm = esgn * expf(-d / b);
        }
        #pragma unroll
        for (int off = 16; off > 0; off >>= 1)
            hterm += __shfl_xor_sync(0xffffffffu, hterm, off);

        if (lane == 0) h_acc += (double)hterm;
    }

    // ---- block partial + single-pass finish ----
    __shared__ double s_h[WARPS_PER_BLOCK];
    __shared__ bool   s_last;
    if (lane == 0) s_h[warp_id] = h_acc;
    __syncthreads();

    if (threadIdx.x == 0) {
        double sum = 0.0;
        #pragma unroll
        for (int w = 0; w < WARPS_PER_BLOCK; w++) sum += s_h[w];
        g_partials[blockIdx.x] = sum;
        __threadfence();
        int prev = atomicAdd(&g_done, 1);
        s_last = (prev == num_blocks - 1);
    }
    __syncthreads();

    if (s_last) {
        __shared__ double s_r[THREADS];
        double v = 0.0;
        for (int i = threadIdx.x; i < num_blocks; i += THREADS)
            v += g_partials[i];
        s_r[threadIdx.x] = v;
        __syncthreads();
        #pragma unroll
        for (int off = THREADS / 2; off > 0; off >>= 1) {
            if (threadIdx.x < off) s_r[threadIdx.x] += s_r[threadIdx.x + off];
            __syncthreads();
        }
        if (threadIdx.x == 0) {
            out[0] = (float)(s_r[0] / (double)m2);
            g_done = 0;               // reset for next graph replay
            __threadfence();
        }
    }
}

extern "C" void kernel_launch(void* const* d_in, const int* in_sizes, int n_in,
                              void* d_out, int out_size)
{
    const float* source = (const float*)d_in[0];
    const float* target = (const float*)d_in[1];
    float* out = (float*)d_out;

    const int m  = in_sizes[0] / D;   // 65536
    const int m2 = m / 2;             // 32768

    mmd_fused_kernel<<<GRID_BLOCKS, THREADS>>>(source, target, out, m2, GRID_BLOCKS);
}